// round 6
// baseline (speedup 1.0000x reference)
#include <cuda_runtime.h>
#include <math.h>

// Problem shape (fixed by the dataset)
#define N_SAMPLES 65536
#define KPTS      133
#define FPS       (KPTS * 3)            // 399 floats per sample per tensor

#define SAMPLES_PER_BLOCK 8
#define BLOCK_THREADS     256           // 8 warps, warp-per-sample
#define NBLOCKS           (N_SAMPLES / SAMPLES_PER_BLOCK)   // 8192
#define FLOATS_PER_BLOCK  (SAMPLES_PER_BLOCK * FPS)         // 3192
#define VEC4_PER_BLOCK    (FLOATS_PER_BLOCK / 4)            // 798 (exact)

// ---------------------------------------------------------------------------
// Device scratch (static globals — no runtime allocation allowed)
// ---------------------------------------------------------------------------
__device__ float        g_partial[NBLOCKS];   // per-block residual sums
__device__ unsigned int g_count = 0;          // last-block detector (self-resetting)

// ---------------------------------------------------------------------------
// helpers
// ---------------------------------------------------------------------------
// Merge two per-lane accumulators at butterfly level k:
// lanes with (lane&k)==0 end holding x_me + x_partner; set lanes get y sums.
__device__ __forceinline__ float mg(float x, float y, int k, int lane) {
    float keep = (lane & k) ? y : x;
    float send = (lane & k) ? x : y;
    return keep + __shfl_xor_sync(0xffffffffu, send, k);
}

#define WRED(v) do { \
    v += __shfl_xor_sync(0xffffffffu, v, 16); \
    v += __shfl_xor_sync(0xffffffffu, v, 8);  \
    v += __shfl_xor_sync(0xffffffffu, v, 4);  \
    v += __shfl_xor_sync(0xffffffffu, v, 2);  \
    v += __shfl_xor_sync(0xffffffffu, v, 1);  \
} while (0)

template <int P, int Q, int RR>
__device__ __forceinline__ void jrot(float A[3][3], float V[3][3]) {
    float apq = A[P][Q];
    if (fabsf(apq) > 1e-20f) {
        float tau = (A[Q][Q] - A[P][P]) / (2.0f * apq);
        float tt  = copysignf(1.0f, tau) / (fabsf(tau) + sqrtf(fmaf(tau, tau, 1.0f)));
        float c   = rsqrtf(fmaf(tt, tt, 1.0f));
        float sn  = tt * c;
        A[P][P] -= tt * apq;
        A[Q][Q] += tt * apq;
        A[P][Q] = 0.0f; A[Q][P] = 0.0f;
        float arp = A[RR][P], arq = A[RR][Q];
        A[RR][P] = c * arp - sn * arq;  A[P][RR] = A[RR][P];
        A[RR][Q] = sn * arp + c * arq;  A[Q][RR] = A[RR][Q];
#pragma unroll
        for (int r = 0; r < 3; r++) {
            float vp = V[r][P], vq = V[r][Q];
            V[r][P] = c * vp - sn * vq;
            V[r][Q] = sn * vp + c * vq;
        }
    }
}

__device__ __forceinline__ float det3f(const float U[3][3]) {
    return U[0][0] * (U[1][1] * U[2][2] - U[1][2] * U[2][1])
         - U[0][1] * (U[1][0] * U[2][2] - U[1][2] * U[2][0])
         + U[0][2] * (U[1][0] * U[2][1] - U[1][1] * U[2][0]);
}

// point-accumulate for the stats stage
#define STATS_POINT(t0, t1, t2, o0, o1, o2) do { \
    st0 += (t0); st1 += (t1); st2 += (t2);       \
    so0 += (o0); so1 += (o1); so2 += (o2);       \
    stt = fmaf((t0), (t0), fmaf((t1), (t1), fmaf((t2), (t2), stt))); \
    m00 = fmaf((t0), (o0), m00); m01 = fmaf((t0), (o1), m01); m02 = fmaf((t0), (o2), m02); \
    m10 = fmaf((t1), (o0), m10); m11 = fmaf((t1), (o1), m11); m12 = fmaf((t1), (o2), m12); \
    m20 = fmaf((t2), (o0), m20); m21 = fmaf((t2), (o1), m21); m22 = fmaf((t2), (o2), m22); \
} while (0)

// ---------------------------------------------------------------------------
// Single fused kernel: stage data in smem, stats -> SVD -> residual -> global
// reduction done by the last block to finish (deterministic fixed order).
// ---------------------------------------------------------------------------
__global__ __launch_bounds__(BLOCK_THREADS)
void fused_kernel(const float* __restrict__ outp, const float* __restrict__ tgt,
                  float* __restrict__ d_out) {
    __shared__ float4 sh_t4[VEC4_PER_BLOCK];
    __shared__ float4 sh_o4[VEC4_PER_BLOCK];
    __shared__ float  sh_stats[SAMPLES_PER_BLOCK][16];
    __shared__ float  sh_ab[SAMPLES_PER_BLOCK][12];
    __shared__ float  sh_wsum[SAMPLES_PER_BLOCK];
    __shared__ int    sh_is_last;
    __shared__ double sh_red[BLOCK_THREADS];

    const int tid  = threadIdx.x;
    const int warp = tid >> 5;
    const int lane = tid & 31;

    // ---- Stage 1: cooperative vectorized load (one DRAM pass only) ----
    {
        const float4* __restrict__ gt4 =
            (const float4*)(tgt + (size_t)blockIdx.x * FLOATS_PER_BLOCK);
        const float4* __restrict__ go4 =
            (const float4*)(outp + (size_t)blockIdx.x * FLOATS_PER_BLOCK);
        const bool tail = (tid < VEC4_PER_BLOCK - 768);   // 30 tail elements
        float4 rt0 = __ldg(&gt4[tid]);
        float4 rt1 = __ldg(&gt4[tid + 256]);
        float4 rt2 = __ldg(&gt4[tid + 512]);
        float4 ro0 = __ldg(&go4[tid]);
        float4 ro1 = __ldg(&go4[tid + 256]);
        float4 ro2 = __ldg(&go4[tid + 512]);
        float4 rt3 = make_float4(0.f, 0.f, 0.f, 0.f);
        float4 ro3 = make_float4(0.f, 0.f, 0.f, 0.f);
        if (tail) {
            rt3 = __ldg(&gt4[tid + 768]);
            ro3 = __ldg(&go4[tid + 768]);
        }
        sh_t4[tid]        = rt0;
        sh_t4[tid + 256]  = rt1;
        sh_t4[tid + 512]  = rt2;
        sh_o4[tid]        = ro0;
        sh_o4[tid + 256]  = ro1;
        sh_o4[tid + 512]  = ro2;
        if (tail) {
            sh_t4[tid + 768] = rt3;
            sh_o4[tid + 768] = ro3;
        }
    }
    __syncthreads();

    const float* __restrict__ t = (const float*)sh_t4 + warp * FPS;
    const float* __restrict__ o = (const float*)sh_o4 + warp * FPS;

    // ---- Stage 2: warp-per-sample sufficient statistics ----
    {
        float st0 = 0.f, st1 = 0.f, st2 = 0.f;
        float so0 = 0.f, so1 = 0.f, so2 = 0.f;
        float stt = 0.f;
        float m00 = 0.f, m01 = 0.f, m02 = 0.f;
        float m10 = 0.f, m11 = 0.f, m12 = 0.f;
        float m20 = 0.f, m21 = 0.f, m22 = 0.f;

        // points 0..127: 4 unguarded rounds (lane + 96 <= 127 < 133)
#pragma unroll
        for (int j = 0; j < 4; j++) {
            int p = lane + 32 * j;
            float t0 = t[3 * p + 0], t1 = t[3 * p + 1], t2 = t[3 * p + 2];
            float o0 = o[3 * p + 0], o1 = o[3 * p + 1], o2 = o[3 * p + 2];
            STATS_POINT(t0, t1, t2, o0, o1, o2);
        }
        // tail points 128..132
        if (lane < KPTS - 128) {
            int p = 128 + lane;
            float t0 = t[3 * p + 0], t1 = t[3 * p + 1], t2 = t[3 * p + 2];
            float o0 = o[3 * p + 0], o1 = o[3 * p + 1], o2 = o[3 * p + 2];
            STATS_POINT(t0, t1, t2, o0, o1, o2);
        }

        // Merge-tree reduction of all 16 accumulators in 16 shuffles.
        // After this, lane l holds the total of accumulator idx(l).
        float b0 = mg(st0, st1, 16, lane);
        float b1 = mg(st2, so0, 16, lane);
        float b2 = mg(so1, so2, 16, lane);
        float b3 = mg(stt, m00, 16, lane);
        float b4 = mg(m01, m02, 16, lane);
        float b5 = mg(m10, m11, 16, lane);
        float b6 = mg(m12, m20, 16, lane);
        float b7 = mg(m21, m22, 16, lane);

        float c0 = mg(b0, b1, 8, lane);
        float c1 = mg(b2, b3, 8, lane);
        float c2 = mg(b4, b5, 8, lane);
        float c3 = mg(b6, b7, 8, lane);

        float d0 = mg(c0, c1, 4, lane);
        float d1 = mg(c2, c3, 4, lane);

        float e = mg(d0, d1, 2, lane);
        e += __shfl_xor_sync(0xffffffffu, e, 1);

        // acc index held by lane l (bit i of idx chosen at merge level 16>>i):
        int idx = ((lane >> 4) & 1) | (((lane >> 3) & 1) << 1)
                | (((lane >> 2) & 1) << 2) | (((lane >> 1) & 1) << 3);
        if ((lane & 1) == 0) sh_stats[warp][idx] = e;
    }
    __syncthreads();

    // ---- Stage 3: one thread per sample does the 3x3 SVD -> (A, b) ----
    if (tid < SAMPLES_PER_BLOCK) {
        const float* s = sh_stats[tid];
        const float invK = 1.0f / (float)KPTS;
        float st[3]  = {s[0], s[1], s[2]};
        float so[3]  = {s[3], s[4], s[5]};
        float stt    = s[6];
        float M[3][3] = {{s[7],  s[8],  s[9]},
                         {s[10], s[11], s[12]},
                         {s[13], s[14], s[15]}};

        float mu1[3] = {st[0] * invK, st[1] * invK, st[2] * invK};
        float mu2[3] = {so[0] * invK, so[1] * invK, so[2] * invK};

#pragma unroll
        for (int a = 0; a < 3; a++)
#pragma unroll
            for (int b = 0; b < 3; b++)
                M[a][b] = fmaf(-st[a] * invK, so[b], M[a][b]);

        float var1 = stt - (st[0] * st[0] + st[1] * st[1] + st[2] * st[2]) * invK;

        float S[3][3];
#pragma unroll
        for (int i = 0; i < 3; i++)
#pragma unroll
            for (int j = 0; j < 3; j++)
                S[i][j] = M[0][i] * M[0][j] + M[1][i] * M[1][j] + M[2][i] * M[2][j];

        float V[3][3] = {{1.f, 0.f, 0.f}, {0.f, 1.f, 0.f}, {0.f, 0.f, 1.f}};
#pragma unroll
        for (int sw = 0; sw < 4; sw++) {
            jrot<0, 1, 2>(S, V);
            jrot<0, 2, 1>(S, V);
            jrot<1, 2, 0>(S, V);
        }

        float Bc[3][3];
#pragma unroll
        for (int r = 0; r < 3; r++)
#pragma unroll
            for (int i = 0; i < 3; i++)
                Bc[r][i] = M[r][0] * V[0][i] + M[r][1] * V[1][i] + M[r][2] * V[2][i];

        float s0 = sqrtf(Bc[0][0]*Bc[0][0] + Bc[1][0]*Bc[1][0] + Bc[2][0]*Bc[2][0]);
        float s1 = sqrtf(Bc[0][1]*Bc[0][1] + Bc[1][1]*Bc[1][1] + Bc[2][1]*Bc[2][1]);
        float s2 = sqrtf(Bc[0][2]*Bc[0][2] + Bc[1][2]*Bc[1][2] + Bc[2][2]*Bc[2][2]);

        float U[3][3];
        float r0i = 1.0f / fmaxf(s0, 1e-20f);
        float r1i = 1.0f / fmaxf(s1, 1e-20f);
        float r2i = 1.0f / fmaxf(s2, 1e-20f);
#pragma unroll
        for (int r = 0; r < 3; r++) {
            U[r][0] = Bc[r][0] * r0i;
            U[r][1] = Bc[r][1] * r1i;
            U[r][2] = Bc[r][2] * r2i;
        }

        int m = 0; float sm = s0;
        if (s1 < sm) { sm = s1; m = 1; }
        if (s2 < sm) { sm = s2; m = 2; }
        float smax = fmaxf(s0, fmaxf(s1, s2));

        if (sm < 1e-5f * smax + 1e-30f) {
            if (m == 0) {
                U[0][0] = U[1][1]*U[2][2] - U[2][1]*U[1][2];
                U[1][0] = U[2][1]*U[0][2] - U[0][1]*U[2][2];
                U[2][0] = U[0][1]*U[1][2] - U[1][1]*U[0][2];
            } else if (m == 1) {
                U[0][1] = U[1][2]*U[2][0] - U[2][2]*U[1][0];
                U[1][1] = U[2][2]*U[0][0] - U[0][2]*U[2][0];
                U[2][1] = U[0][2]*U[1][0] - U[1][2]*U[0][0];
            } else {
                U[0][2] = U[1][0]*U[2][1] - U[2][0]*U[1][1];
                U[1][2] = U[2][0]*U[0][1] - U[0][0]*U[2][1];
                U[2][2] = U[0][0]*U[1][1] - U[1][0]*U[0][1];
            }
        }

        float detU = det3f(U);
        float detV = det3f(V);
        float dsign = (detU * detV < 0.0f) ? -1.0f : 1.0f;

        float scale = (s0 + s1 + s2 + (dsign - 1.0f) * sm) / var1;

        float f0 = (m == 0) ? dsign : 1.0f;
        float f1 = (m == 1) ? dsign : 1.0f;
        float f2 = (m == 2) ? dsign : 1.0f;

        float Aab[3][3];
#pragma unroll
        for (int a = 0; a < 3; a++)
#pragma unroll
            for (int b = 0; b < 3; b++)
                Aab[a][b] = scale * (f0 * V[a][0] * U[b][0] +
                                     f1 * V[a][1] * U[b][1] +
                                     f2 * V[a][2] * U[b][2]);

        float* ab = sh_ab[tid];
        ab[0] = Aab[0][0]; ab[1] = Aab[0][1]; ab[2] = Aab[0][2];
        ab[3] = Aab[1][0]; ab[4] = Aab[1][1]; ab[5] = Aab[1][2];
        ab[6] = Aab[2][0]; ab[7] = Aab[2][1]; ab[8] = Aab[2][2];
#pragma unroll
        for (int a = 0; a < 3; a++)
            ab[9 + a] = mu2[a] - (Aab[a][0]*mu1[0] + Aab[a][1]*mu1[1] + Aab[a][2]*mu1[2]);
    }
    __syncthreads();

    // ---- Stage 4: warp-per-sample residual from smem ----
    {
        const float* ab = sh_ab[warp];
        const float a00 = ab[0], a01 = ab[1], a02 = ab[2];
        const float a10 = ab[3], a11 = ab[4], a12 = ab[5];
        const float a20 = ab[6], a21 = ab[7], a22 = ab[8];
        const float b0 = ab[9], b1 = ab[10], b2 = ab[11];

        float acc = 0.0f;
#pragma unroll
        for (int j = 0; j < 4; j++) {
            int p = lane + 32 * j;
            float t0 = t[3 * p + 0], t1 = t[3 * p + 1], t2 = t[3 * p + 2];
            float o0 = o[3 * p + 0], o1 = o[3 * p + 1], o2 = o[3 * p + 2];
            float p0 = fmaf(a00, t0, fmaf(a01, t1, fmaf(a02, t2, b0)));
            float p1 = fmaf(a10, t0, fmaf(a11, t1, fmaf(a12, t2, b1)));
            float p2 = fmaf(a20, t0, fmaf(a21, t1, fmaf(a22, t2, b2)));
            float d0 = o0 - p0, d1 = o1 - p1, d2 = o2 - p2;
            acc += sqrtf(fmaf(d0, d0, fmaf(d1, d1, d2 * d2)));
        }
        if (lane < KPTS - 128) {
            int p = 128 + lane;
            float t0 = t[3 * p + 0], t1 = t[3 * p + 1], t2 = t[3 * p + 2];
            float o0 = o[3 * p + 0], o1 = o[3 * p + 1], o2 = o[3 * p + 2];
            float p0 = fmaf(a00, t0, fmaf(a01, t1, fmaf(a02, t2, b0)));
            float p1 = fmaf(a10, t0, fmaf(a11, t1, fmaf(a12, t2, b1)));
            float p2 = fmaf(a20, t0, fmaf(a21, t1, fmaf(a22, t2, b2)));
            float d0 = o0 - p0, d1 = o1 - p1, d2 = o2 - p2;
            acc += sqrtf(fmaf(d0, d0, fmaf(d1, d1, d2 * d2)));
        }
        WRED(acc);
        if (lane == 0) sh_wsum[warp] = acc;
    }
    __syncthreads();

    // ---- Stage 5: publish block sum; last finishing block reduces all ----
    if (tid == 0) {
        float tot = 0.0f;
#pragma unroll
        for (int w = 0; w < SAMPLES_PER_BLOCK; w++) tot += sh_wsum[w];
        g_partial[blockIdx.x] = tot;
        __threadfence();
        unsigned int prev = atomicAdd(&g_count, 1u);
        sh_is_last = (prev == NBLOCKS - 1);
    }
    __syncthreads();

    if (sh_is_last) {
        __threadfence();   // make all g_partial writes visible to this block
        const float4* p4 = (const float4*)g_partial;   // 2048 float4
        double acc = 0.0;
#pragma unroll
        for (int k = 0; k < 8; k++) {
            float4 v = p4[tid + 256 * k];
            acc += (double)v.x + (double)v.y + (double)v.z + (double)v.w;
        }
        sh_red[tid] = acc;
        __syncthreads();
#pragma unroll
        for (int s = 128; s > 0; s >>= 1) {
            if (tid < s) sh_red[tid] += sh_red[tid + s];
            __syncthreads();
        }
        if (tid == 0) {
            double mean = sh_red[0] / ((double)N_SAMPLES * (double)KPTS);
            d_out[0] = (float)mean;   // LOSS_WEIGHT = 1.0
            g_count = 0;              // reset for next graph replay
        }
    }
}

// ---------------------------------------------------------------------------
// Launch
// ---------------------------------------------------------------------------
extern "C" void kernel_launch(void* const* d_in, const int* in_sizes, int n_in,
                              void* d_out, int out_size) {
    (void)in_sizes; (void)n_in; (void)out_size;
    const float* output = (const float*)d_in[0];
    const float* target = (const float*)d_in[1];

    fused_kernel<<<NBLOCKS, BLOCK_THREADS>>>(output, target, (float*)d_out);
}

// round 7
// speedup vs baseline: 1.1423x; 1.1423x over previous
#include <cuda_runtime.h>
#include <math.h>

// Problem shape (fixed by the dataset)
#define N_SAMPLES 65536
#define KPTS      133
#define FPS       (KPTS * 3)            // 399 floats per sample per tensor

#define SAMPLES_PER_BLOCK 4
#define BLOCK_THREADS     128           // 4 warps, warp-per-sample
#define NBLOCKS           (N_SAMPLES / SAMPLES_PER_BLOCK)   // 16384
#define FLOATS_PER_BLOCK  (SAMPLES_PER_BLOCK * FPS)         // 1596
#define VEC4_PER_BLOCK    (FLOATS_PER_BLOCK / 4)            // 399 (exact)

// ---------------------------------------------------------------------------
// Device scratch (static globals — no runtime allocation allowed)
// ---------------------------------------------------------------------------
__device__ float        g_partial[NBLOCKS];   // per-block residual sums (64 KB)
__device__ unsigned int g_count = 0;          // last-block detector (self-resetting)

// ---------------------------------------------------------------------------
// helpers
// ---------------------------------------------------------------------------
// Merge two per-lane accumulators at butterfly level k:
// lanes with (lane&k)==0 end holding x sums; set lanes end holding y sums.
__device__ __forceinline__ float mg(float x, float y, int k, int lane) {
    float keep = (lane & k) ? y : x;
    float send = (lane & k) ? x : y;
    return keep + __shfl_xor_sync(0xffffffffu, send, k);
}

#define WRED(v) do { \
    v += __shfl_xor_sync(0xffffffffu, v, 16); \
    v += __shfl_xor_sync(0xffffffffu, v, 8);  \
    v += __shfl_xor_sync(0xffffffffu, v, 4);  \
    v += __shfl_xor_sync(0xffffffffu, v, 2);  \
    v += __shfl_xor_sync(0xffffffffu, v, 1);  \
} while (0)

template <int P, int Q, int RR>
__device__ __forceinline__ void jrot(float A[3][3], float V[3][3]) {
    float apq = A[P][Q];
    if (fabsf(apq) > 1e-20f) {
        float tau = __fdividef(A[Q][Q] - A[P][P], 2.0f * apq);
        float tt  = __fdividef(copysignf(1.0f, tau),
                               fabsf(tau) + sqrtf(fmaf(tau, tau, 1.0f)));
        float c   = rsqrtf(fmaf(tt, tt, 1.0f));
        float sn  = tt * c;
        A[P][P] -= tt * apq;
        A[Q][Q] += tt * apq;
        A[P][Q] = 0.0f; A[Q][P] = 0.0f;
        float arp = A[RR][P], arq = A[RR][Q];
        A[RR][P] = c * arp - sn * arq;  A[P][RR] = A[RR][P];
        A[RR][Q] = sn * arp + c * arq;  A[Q][RR] = A[RR][Q];
#pragma unroll
        for (int r = 0; r < 3; r++) {
            float vp = V[r][P], vq = V[r][Q];
            V[r][P] = c * vp - sn * vq;
            V[r][Q] = sn * vp + c * vq;
        }
    }
}

__device__ __forceinline__ float det3f(const float U[3][3]) {
    return U[0][0] * (U[1][1] * U[2][2] - U[1][2] * U[2][1])
         - U[0][1] * (U[1][0] * U[2][2] - U[1][2] * U[2][0])
         + U[0][2] * (U[1][0] * U[2][1] - U[1][1] * U[2][0]);
}

// point-accumulate for the stats stage
#define STATS_POINT(t0, t1, t2, o0, o1, o2) do { \
    st0 += (t0); st1 += (t1); st2 += (t2);       \
    so0 += (o0); so1 += (o1); so2 += (o2);       \
    stt = fmaf((t0), (t0), fmaf((t1), (t1), fmaf((t2), (t2), stt))); \
    m00 = fmaf((t0), (o0), m00); m01 = fmaf((t0), (o1), m01); m02 = fmaf((t0), (o2), m02); \
    m10 = fmaf((t1), (o0), m10); m11 = fmaf((t1), (o1), m11); m12 = fmaf((t1), (o2), m12); \
    m20 = fmaf((t2), (o0), m20); m21 = fmaf((t2), (o1), m21); m22 = fmaf((t2), (o2), m22); \
} while (0)

// ---------------------------------------------------------------------------
// Single fused kernel: stage data in smem, stats -> SVD -> residual -> global
// reduction by the last finishing block (deterministic fixed order).
// 128 threads / 4 samples per block; launch_bounds presses regs to ~40 so
// 12 blocks (48 warps) fit per SM.
// ---------------------------------------------------------------------------
__global__ __launch_bounds__(BLOCK_THREADS, 12)
void fused_kernel(const float* __restrict__ outp, const float* __restrict__ tgt,
                  float* __restrict__ d_out) {
    __shared__ float4 sh_t4[VEC4_PER_BLOCK];
    __shared__ float4 sh_o4[VEC4_PER_BLOCK];
    __shared__ float  sh_stats[SAMPLES_PER_BLOCK][16];
    __shared__ float  sh_ab[SAMPLES_PER_BLOCK][12];
    __shared__ float  sh_wsum[SAMPLES_PER_BLOCK];
    __shared__ int    sh_is_last;
    __shared__ double sh_red[BLOCK_THREADS];

    const int tid  = threadIdx.x;
    const int warp = tid >> 5;
    const int lane = tid & 31;

    // ---- Stage 1: cooperative vectorized load (one DRAM pass only) ----
    // 399 float4 per tensor: 3 full rounds of 128 + 15-wide tail.
    {
        const float4* __restrict__ gt4 =
            (const float4*)(tgt + (size_t)blockIdx.x * FLOATS_PER_BLOCK);
        const float4* __restrict__ go4 =
            (const float4*)(outp + (size_t)blockIdx.x * FLOATS_PER_BLOCK);
        const bool tail = (tid < VEC4_PER_BLOCK - 384);   // 15 tail elements
        float4 rt0 = __ldg(&gt4[tid]);
        float4 rt1 = __ldg(&gt4[tid + 128]);
        float4 rt2 = __ldg(&gt4[tid + 256]);
        float4 ro0 = __ldg(&go4[tid]);
        float4 ro1 = __ldg(&go4[tid + 128]);
        float4 ro2 = __ldg(&go4[tid + 256]);
        float4 rt3 = make_float4(0.f, 0.f, 0.f, 0.f);
        float4 ro3 = make_float4(0.f, 0.f, 0.f, 0.f);
        if (tail) {
            rt3 = __ldg(&gt4[tid + 384]);
            ro3 = __ldg(&go4[tid + 384]);
        }
        sh_t4[tid]        = rt0;
        sh_t4[tid + 128]  = rt1;
        sh_t4[tid + 256]  = rt2;
        sh_o4[tid]        = ro0;
        sh_o4[tid + 128]  = ro1;
        sh_o4[tid + 256]  = ro2;
        if (tail) {
            sh_t4[tid + 384] = rt3;
            sh_o4[tid + 384] = ro3;
        }
    }
    __syncthreads();

    const float* __restrict__ t = (const float*)sh_t4 + warp * FPS;
    const float* __restrict__ o = (const float*)sh_o4 + warp * FPS;

    // ---- Stage 2: warp-per-sample sufficient statistics ----
    {
        float st0 = 0.f, st1 = 0.f, st2 = 0.f;
        float so0 = 0.f, so1 = 0.f, so2 = 0.f;
        float stt = 0.f;
        float m00 = 0.f, m01 = 0.f, m02 = 0.f;
        float m10 = 0.f, m11 = 0.f, m12 = 0.f;
        float m20 = 0.f, m21 = 0.f, m22 = 0.f;

        // points 0..127: 4 unguarded rounds (lane + 96 <= 127 < 133)
#pragma unroll
        for (int j = 0; j < 4; j++) {
            int p = lane + 32 * j;
            float t0 = t[3 * p + 0], t1 = t[3 * p + 1], t2 = t[3 * p + 2];
            float o0 = o[3 * p + 0], o1 = o[3 * p + 1], o2 = o[3 * p + 2];
            STATS_POINT(t0, t1, t2, o0, o1, o2);
        }
        // tail points 128..132
        if (lane < KPTS - 128) {
            int p = 128 + lane;
            float t0 = t[3 * p + 0], t1 = t[3 * p + 1], t2 = t[3 * p + 2];
            float o0 = o[3 * p + 0], o1 = o[3 * p + 1], o2 = o[3 * p + 2];
            STATS_POINT(t0, t1, t2, o0, o1, o2);
        }

        // Merge-tree reduction of all 16 accumulators in 16 shuffles.
        float b0 = mg(st0, st1, 16, lane);
        float b1 = mg(st2, so0, 16, lane);
        float b2 = mg(so1, so2, 16, lane);
        float b3 = mg(stt, m00, 16, lane);
        float b4 = mg(m01, m02, 16, lane);
        float b5 = mg(m10, m11, 16, lane);
        float b6 = mg(m12, m20, 16, lane);
        float b7 = mg(m21, m22, 16, lane);

        float c0 = mg(b0, b1, 8, lane);
        float c1 = mg(b2, b3, 8, lane);
        float c2 = mg(b4, b5, 8, lane);
        float c3 = mg(b6, b7, 8, lane);

        float d0 = mg(c0, c1, 4, lane);
        float d1 = mg(c2, c3, 4, lane);

        float e = mg(d0, d1, 2, lane);
        e += __shfl_xor_sync(0xffffffffu, e, 1);

        // acc index held by lane l (bit i of idx chosen at merge level 16>>i):
        int idx = ((lane >> 4) & 1) | (((lane >> 3) & 1) << 1)
                | (((lane >> 2) & 1) << 2) | (((lane >> 1) & 1) << 3);
        if ((lane & 1) == 0) sh_stats[warp][idx] = e;
    }
    __syncthreads();

    // ---- Stage 3: one thread per sample does the 3x3 SVD -> (A, b) ----
    if (tid < SAMPLES_PER_BLOCK) {
        const float* s = sh_stats[tid];
        const float invK = 1.0f / (float)KPTS;
        float st[3]  = {s[0], s[1], s[2]};
        float so[3]  = {s[3], s[4], s[5]};
        float stt    = s[6];
        float M[3][3] = {{s[7],  s[8],  s[9]},
                         {s[10], s[11], s[12]},
                         {s[13], s[14], s[15]}};

        float mu1[3] = {st[0] * invK, st[1] * invK, st[2] * invK};
        float mu2[3] = {so[0] * invK, so[1] * invK, so[2] * invK};

#pragma unroll
        for (int a = 0; a < 3; a++)
#pragma unroll
            for (int b = 0; b < 3; b++)
                M[a][b] = fmaf(-st[a] * invK, so[b], M[a][b]);

        float var1 = stt - (st[0] * st[0] + st[1] * st[1] + st[2] * st[2]) * invK;

        float S[3][3];
#pragma unroll
        for (int i = 0; i < 3; i++)
#pragma unroll
            for (int j = 0; j < 3; j++)
                S[i][j] = M[0][i] * M[0][j] + M[1][i] * M[1][j] + M[2][i] * M[2][j];

        float V[3][3] = {{1.f, 0.f, 0.f}, {0.f, 1.f, 0.f}, {0.f, 0.f, 1.f}};
#pragma unroll
        for (int sw = 0; sw < 4; sw++) {
            jrot<0, 1, 2>(S, V);
            jrot<0, 2, 1>(S, V);
            jrot<1, 2, 0>(S, V);
        }

        float Bc[3][3];
#pragma unroll
        for (int r = 0; r < 3; r++)
#pragma unroll
            for (int i = 0; i < 3; i++)
                Bc[r][i] = M[r][0] * V[0][i] + M[r][1] * V[1][i] + M[r][2] * V[2][i];

        float s0 = sqrtf(Bc[0][0]*Bc[0][0] + Bc[1][0]*Bc[1][0] + Bc[2][0]*Bc[2][0]);
        float s1 = sqrtf(Bc[0][1]*Bc[0][1] + Bc[1][1]*Bc[1][1] + Bc[2][1]*Bc[2][1]);
        float s2 = sqrtf(Bc[0][2]*Bc[0][2] + Bc[1][2]*Bc[1][2] + Bc[2][2]*Bc[2][2]);

        float U[3][3];
        float r0i = __fdividef(1.0f, fmaxf(s0, 1e-20f));
        float r1i = __fdividef(1.0f, fmaxf(s1, 1e-20f));
        float r2i = __fdividef(1.0f, fmaxf(s2, 1e-20f));
#pragma unroll
        for (int r = 0; r < 3; r++) {
            U[r][0] = Bc[r][0] * r0i;
            U[r][1] = Bc[r][1] * r1i;
            U[r][2] = Bc[r][2] * r2i;
        }

        int m = 0; float sm = s0;
        if (s1 < sm) { sm = s1; m = 1; }
        if (s2 < sm) { sm = s2; m = 2; }
        float smax = fmaxf(s0, fmaxf(s1, s2));

        if (sm < 1e-5f * smax + 1e-30f) {
            if (m == 0) {
                U[0][0] = U[1][1]*U[2][2] - U[2][1]*U[1][2];
                U[1][0] = U[2][1]*U[0][2] - U[0][1]*U[2][2];
                U[2][0] = U[0][1]*U[1][2] - U[1][1]*U[0][2];
            } else if (m == 1) {
                U[0][1] = U[1][2]*U[2][0] - U[2][2]*U[1][0];
                U[1][1] = U[2][2]*U[0][0] - U[0][2]*U[2][0];
                U[2][1] = U[0][2]*U[1][0] - U[1][2]*U[0][0];
            } else {
                U[0][2] = U[1][0]*U[2][1] - U[2][0]*U[1][1];
                U[1][2] = U[2][0]*U[0][1] - U[0][0]*U[2][1];
                U[2][2] = U[0][0]*U[1][1] - U[1][0]*U[0][1];
            }
        }

        float detU = det3f(U);
        float detV = det3f(V);
        float dsign = (detU * detV < 0.0f) ? -1.0f : 1.0f;

        float scale = __fdividef(s0 + s1 + s2 + (dsign - 1.0f) * sm, var1);

        float f0 = (m == 0) ? dsign : 1.0f;
        float f1 = (m == 1) ? dsign : 1.0f;
        float f2 = (m == 2) ? dsign : 1.0f;

        float Aab[3][3];
#pragma unroll
        for (int a = 0; a < 3; a++)
#pragma unroll
            for (int b = 0; b < 3; b++)
                Aab[a][b] = scale * (f0 * V[a][0] * U[b][0] +
                                     f1 * V[a][1] * U[b][1] +
                                     f2 * V[a][2] * U[b][2]);

        float* ab = sh_ab[tid];
        ab[0] = Aab[0][0]; ab[1] = Aab[0][1]; ab[2] = Aab[0][2];
        ab[3] = Aab[1][0]; ab[4] = Aab[1][1]; ab[5] = Aab[1][2];
        ab[6] = Aab[2][0]; ab[7] = Aab[2][1]; ab[8] = Aab[2][2];
#pragma unroll
        for (int a = 0; a < 3; a++)
            ab[9 + a] = mu2[a] - (Aab[a][0]*mu1[0] + Aab[a][1]*mu1[1] + Aab[a][2]*mu1[2]);
    }
    __syncthreads();

    // ---- Stage 4: warp-per-sample residual from smem ----
    {
        const float* ab = sh_ab[warp];
        const float a00 = ab[0], a01 = ab[1], a02 = ab[2];
        const float a10 = ab[3], a11 = ab[4], a12 = ab[5];
        const float a20 = ab[6], a21 = ab[7], a22 = ab[8];
        const float b0 = ab[9], b1 = ab[10], b2 = ab[11];

        float acc = 0.0f;
#pragma unroll
        for (int j = 0; j < 4; j++) {
            int p = lane + 32 * j;
            float t0 = t[3 * p + 0], t1 = t[3 * p + 1], t2 = t[3 * p + 2];
            float o0 = o[3 * p + 0], o1 = o[3 * p + 1], o2 = o[3 * p + 2];
            float p0 = fmaf(a00, t0, fmaf(a01, t1, fmaf(a02, t2, b0)));
            float p1 = fmaf(a10, t0, fmaf(a11, t1, fmaf(a12, t2, b1)));
            float p2 = fmaf(a20, t0, fmaf(a21, t1, fmaf(a22, t2, b2)));
            float d0 = o0 - p0, d1 = o1 - p1, d2 = o2 - p2;
            float dd = fmaf(d0, d0, fmaf(d1, d1, d2 * d2));
            acc += dd * rsqrtf(fmaxf(dd, 1e-30f));   // |d|, approx (err ~1e-7)
        }
        if (lane < KPTS - 128) {
            int p = 128 + lane;
            float t0 = t[3 * p + 0], t1 = t[3 * p + 1], t2 = t[3 * p + 2];
            float o0 = o[3 * p + 0], o1 = o[3 * p + 1], o2 = o[3 * p + 2];
            float p0 = fmaf(a00, t0, fmaf(a01, t1, fmaf(a02, t2, b0)));
            float p1 = fmaf(a10, t0, fmaf(a11, t1, fmaf(a12, t2, b1)));
            float p2 = fmaf(a20, t0, fmaf(a21, t1, fmaf(a22, t2, b2)));
            float d0 = o0 - p0, d1 = o1 - p1, d2 = o2 - p2;
            float dd = fmaf(d0, d0, fmaf(d1, d1, d2 * d2));
            acc += dd * rsqrtf(fmaxf(dd, 1e-30f));
        }
        WRED(acc);
        if (lane == 0) sh_wsum[warp] = acc;
    }
    __syncthreads();

    // ---- Stage 5: publish block sum; last finishing block reduces all ----
    if (tid == 0) {
        float tot = 0.0f;
#pragma unroll
        for (int w = 0; w < SAMPLES_PER_BLOCK; w++) tot += sh_wsum[w];
        g_partial[blockIdx.x] = tot;
        __threadfence();
        unsigned int prev = atomicAdd(&g_count, 1u);
        sh_is_last = (prev == NBLOCKS - 1);
    }
    __syncthreads();

    if (sh_is_last) {
        __threadfence();   // make all g_partial writes visible to this block
        const float4* p4 = (const float4*)g_partial;   // 4096 float4
        double acc = 0.0;
#pragma unroll
        for (int k = 0; k < 32; k++) {
            float4 v = p4[tid + 128 * k];
            acc += (double)v.x + (double)v.y + (double)v.z + (double)v.w;
        }
        sh_red[tid] = acc;
        __syncthreads();
#pragma unroll
        for (int s = 64; s > 0; s >>= 1) {
            if (tid < s) sh_red[tid] += sh_red[tid + s];
            __syncthreads();
        }
        if (tid == 0) {
            double mean = sh_red[0] / ((double)N_SAMPLES * (double)KPTS);
            d_out[0] = (float)mean;   // LOSS_WEIGHT = 1.0
            g_count = 0;              // reset for next graph replay
        }
    }
}

// ---------------------------------------------------------------------------
// Launch
// ---------------------------------------------------------------------------
extern "C" void kernel_launch(void* const* d_in, const int* in_sizes, int n_in,
                              void* d_out, int out_size) {
    (void)in_sizes; (void)n_in; (void)out_size;
    const float* output = (const float*)d_in[0];
    const float* target = (const float*)d_in[1];

    fused_kernel<<<NBLOCKS, BLOCK_THREADS>>>(output, target, (float*)d_out);
}